// round 16
// baseline (speedup 1.0000x reference)
#include <cuda_runtime.h>
#include <cuda_bf16.h>
#include <cuda_fp16.h>

#define NMAX 100000
#define EMAX 3200000
#define DD 256
#define CC 40

typedef unsigned int u32;
typedef unsigned short u16;

struct __align__(8) EdgeRec { int src; float nrm; };

// ---- static device scratch (allocation-free rule) ----
__device__ int   g_is64;
__device__ int   g_deg[NMAX];
__device__ int   g_off[NMAX + 1];
__device__ int   g_cur[NMAX];
__device__ float g_dinv[NMAX];
__device__ EdgeRec g_edges[EMAX];
__device__ __align__(128) unsigned char g_T8[(size_t)NMAX * DD];  // GEMM output, e4m3
__device__ __align__(128) __half g_Af[(size_t)NMAX * DD];   // prop output (activations), fp16
__device__ __align__(128) __half g_Xf[(size_t)NMAX * DD];   // input x, fp16
__device__ __align__(128) __half g_Whf[3 * DD * DD];        // W^T, fp16
__device__ __align__(128) __half g_Zh[3][(size_t)NMAX * CC];  // [0]=z0, [1]/[2]=ping-pong

// ---- fp8 e4m3 pack/unpack ----
__device__ __forceinline__ u16 pack_e4m3(float lo, float hi) {
    u16 r;
    asm("cvt.rn.satfinite.e4m3x2.f32 %0, %1, %2;" : "=h"(r) : "f"(hi), "f"(lo));
    return r;
}
__device__ __forceinline__ float2 up8(u16 p) {
    u32 h2b;
    asm("cvt.rn.f16x2.e4m3x2 %0, %1;" : "=r"(h2b) : "h"(p));
    return __half22float2(*(__half2*)&h2b);
}

// ======================= preprocessing =======================
__global__ void k_detect(const long long* ei, int e, int n) {
    __shared__ int bad;
    if (threadIdx.x == 0) bad = 0;
    __syncthreads();
    int m = e < 2048 ? e : 2048;
    int isbad = 0;
    for (int i = threadIdx.x; i < m; i += blockDim.x) {
        long long v = ei[i];
        if (v < 0 || v >= (long long)n) isbad = 1;
    }
    if (isbad) atomicOr(&bad, 1);
    __syncthreads();
    if (threadIdx.x == 0) g_is64 = bad ? 0 : 1;
}

__global__ void k_zero_deg(int n) {
    int i = blockIdx.x * blockDim.x + threadIdx.x;
    if (i < n) g_deg[i] = 0;
}

__global__ void k_hist(const void* ei, int e) {
    int f = g_is64;
    const long long* p64 = (const long long*)ei;
    const int* p32 = (const int*)ei;
    int stride = gridDim.x * blockDim.x;
    for (int i = blockIdx.x * blockDim.x + threadIdx.x; i < e; i += stride) {
        int d = f ? (int)p64[e + i] : p32[e + i];
        atomicAdd(&g_deg[d], 1);
    }
}

__global__ void k_dinv(int n) {
    int i = blockIdx.x * blockDim.x + threadIdx.x;
    if (i < n) g_dinv[i] = rsqrtf((float)(g_deg[i] + 1));
}

__global__ void k_scan(int n) {
    __shared__ int s[1024];
    int t = threadIdx.x;
    int chunk = (n + 1023) >> 10;
    int lo = t * chunk; if (lo > n) lo = n;
    int hi = lo + chunk; if (hi > n) hi = n;
    int sum = 0;
    for (int i = lo; i < hi; i++) sum += g_deg[i];
    s[t] = sum;
    __syncthreads();
    for (int off = 1; off < 1024; off <<= 1) {
        int v = 0;
        if (t >= off) v = s[t - off];
        __syncthreads();
        if (t >= off) s[t] += v;
        __syncthreads();
    }
    int run = s[t] - sum;
    for (int i = lo; i < hi; i++) {
        g_off[i] = run; g_cur[i] = run;
        run += g_deg[i];
    }
    if (t == 0) g_off[n] = s[1023];
}

__global__ void k_fill(const void* ei, int e) {
    int f = g_is64;
    const long long* p64 = (const long long*)ei;
    const int* p32 = (const int*)ei;
    int stride = gridDim.x * blockDim.x;
    for (int i = blockIdx.x * blockDim.x + threadIdx.x; i < e; i += stride) {
        int s, d;
        if (f) { s = (int)p64[i]; d = (int)p64[e + i]; }
        else   { s = p32[i];      d = p32[e + i]; }
        int pos = atomicAdd(&g_cur[d], 1);
        EdgeRec r; r.src = s; r.nrm = g_dinv[s] * g_dinv[d];
        g_edges[pos] = r;
    }
}

// ======================= fp16 conversions =======================
__global__ void k_split(const float* __restrict__ X, int total) {
    int i = blockIdx.x * blockDim.x + threadIdx.x;
    if (i < total) g_Xf[i] = __float2half(X[i]);
}

// W [K=256, N=256] row-major -> W^T fp16 [N][K] at layer slot
__global__ void k_wsplit(const float* __restrict__ W, int layer) {
    int i = blockIdx.x * blockDim.x + threadIdx.x;   // 65536
    int k = i >> 8;
    int n = i & 255;
    g_Whf[layer * (DD * DD) + n * DD + k] = __float2half(W[i]);
}

// ======================= fp16 GEMM: mma.sync + ldmatrix + cp.async double buffer =====
// g_T8[M,256] = e4m3( A[M,256] @ W^T )  (W stored [N=256][K=256] K-major)
// CTA tile 128x128, 8 warps of 64x32, K staged 32 wide, 2 smem buffers, 2 CTAs/SM.
#define PAD 40
#define MATB (128 * PAD * 2)               // bytes per matrix per stage = 10240
#define STGB (2 * MATB)                    // bytes per stage (A,B) = 20480
#define SMEM_MMA_TOTAL (2 * STGB)          // 40960 bytes

__device__ __forceinline__ u32 s2u(const void* p) {
    u32 a;
    asm("{ .reg .u64 t; cvta.to.shared.u64 t, %1; cvt.u32.u64 %0, t; }" : "=r"(a) : "l"(p));
    return a;
}

__device__ __forceinline__ void cpa16(u32 dst, const __half* src, int sz) {
    asm volatile("cp.async.cg.shared.global [%0], [%1], 16, %2;"
                 :: "r"(dst), "l"(src), "r"(sz));
}
#define CP_COMMIT() asm volatile("cp.async.commit_group;" ::: "memory")
#define CP_WAIT1()  asm volatile("cp.async.wait_group 1;" ::: "memory")
#define CP_WAIT0()  asm volatile("cp.async.wait_group 0;" ::: "memory")

__device__ __forceinline__ void ldsm_x4(u32* r, u32 saddr) {
    asm volatile("ldmatrix.sync.aligned.m8n8.x4.shared.b16 {%0,%1,%2,%3}, [%4];"
                 : "=r"(r[0]), "=r"(r[1]), "=r"(r[2]), "=r"(r[3]) : "r"(saddr));
}

#define MMA_F16(d, a, b) \
    asm volatile( \
        "mma.sync.aligned.m16n8k16.row.col.f32.f16.f16.f32 " \
        "{%0,%1,%2,%3}, {%4,%5,%6,%7}, {%8,%9}, {%0,%1,%2,%3};" \
        : "+f"((d)[0]), "+f"((d)[1]), "+f"((d)[2]), "+f"((d)[3]) \
        : "r"((a)[0]), "r"((a)[1]), "r"((a)[2]), "r"((a)[3]), \
          "r"((b)[0]), "r"((b)[1]))

__global__ void __launch_bounds__(256, 2) k_mma(int srcX, int layer, int M)
{
    extern __shared__ __half sm[];
    u32 sb = s2u(sm);

    const __half* A = srcX ? g_Xf : g_Af;
    const __half* B = g_Whf + layer * (DD * DD);

    int tid = threadIdx.x;
    int wid = tid >> 5;
    int lane = tid & 31;
    int g = lane >> 2;
    int tg = lane & 3;
    int wm = (wid & 1) * 64;       // warp row block (64 rows)
    int wn = (wid >> 1) * 32;      // warp col block (32 cols)
    int mBase = blockIdx.y * 128;
    int nBase = blockIdx.x * 128;

    float acc[16][4];
#pragma unroll
    for (int i = 0; i < 16; i++)
#pragma unroll
        for (int j = 0; j < 4; j++) acc[i][j] = 0.f;

    // ---- cp.async stage loader: stage buffer buf, K-offset kc ----
    auto load_stage = [&](int buf, int kc) {
        u32 so = sb + (u32)(buf * STGB);
#pragma unroll
        for (int it = tid; it < 512; it += 256) {
            int r = it >> 2;
            int c = (it & 3) * 8;
            int row = mBase + r;
            int sz = (row < M) ? 16 : 0;
            int rc = (row < M) ? row : 0;
            size_t go = (size_t)rc * DD + kc + c;
            u32 d = so + (u32)((r * PAD + c) * 2);
            cpa16(d, A + go, sz);
        }
#pragma unroll
        for (int it = tid; it < 512; it += 256) {
            int r = it >> 2;
            int c = (it & 3) * 8;
            size_t go = (size_t)(nBase + r) * DD + kc + c;
            u32 d = so + (u32)((r * PAD + c) * 2);
            cpa16(d + MATB, B + go, 16);
        }
    };

    load_stage(0, 0);  CP_COMMIT();
    load_stage(1, 32); CP_COMMIT();

    // ldmatrix lane addressing (constant per thread)
    int a_row = (lane & 15);
    int a_k   = (lane >> 4) << 3;
    int b_n   = ((lane >> 4) & 1) * 8 + (lane & 7);
    int b_k   = ((lane >> 3) & 1) << 3;

    for (int s = 0; s < 8; s++) {
        if (s == 7) { CP_WAIT0(); } else { CP_WAIT1(); }
        __syncthreads();
        u32 bufo = sb + (u32)((s & 1) * STGB);
#pragma unroll
        for (int k16 = 0; k16 < 32; k16 += 16) {
            u32 af[4][4], bf[8];
#pragma unroll
            for (int mi = 0; mi < 4; mi++) {
                u32 ad = bufo + (u32)(((wm + mi * 16 + a_row) * PAD + k16 + a_k) * 2);
                ldsm_x4(af[mi], ad);
            }
#pragma unroll
            for (int nb = 0; nb < 2; nb++) {
                u32 bd = bufo + (u32)(((wn + nb * 16 + b_n) * PAD + k16 + b_k) * 2);
                ldsm_x4(bf + nb * 4, bd + MATB);
            }
#pragma unroll
            for (int mi = 0; mi < 4; mi++)
#pragma unroll
                for (int ni = 0; ni < 4; ni++)
                    MMA_F16(acc[mi * 4 + ni], af[mi], bf + ni * 2);
        }
        __syncthreads();
        if (s + 2 < 8) {
            load_stage(s & 1, (s + 2) * 32);
            CP_COMMIT();
        }
    }

    // epilogue: write e4m3 (low byte = col, high byte = col+1)
#pragma unroll
    for (int mi = 0; mi < 4; mi++) {
#pragma unroll
        for (int ni = 0; ni < 4; ni++) {
            int m0 = mBase + wm + mi * 16 + g;
            int col = nBase + wn + ni * 8 + 2 * tg;
            float* d = acc[mi * 4 + ni];
            if (m0 < M)
                *(u16*)(g_T8 + (size_t)m0 * DD + col) = pack_e4m3(d[0], d[1]);
            if (m0 + 8 < M)
                *(u16*)(g_T8 + (size_t)(m0 + 8) * DD + col) = pack_e4m3(d[2], d[3]);
        }
    }
}

// ======================= GCN propagate (single pass, fp8 gather, unroll 4) ============
// out = relu(A_hat @ T8 + b) -> fp16. block = node; warp w handles edges beg+w+4k;
// each warp gathers the full 256B fp8 row as 32 x 8B; smem reduce.
__global__ void __launch_bounds__(128) k_prop_gcn(const float* __restrict__ bias)
{
    __shared__ float red[4][DD];
    int i = blockIdx.x;
    int w = threadIdx.x >> 5;
    int lane = threadIdx.x & 31;
    int beg = g_off[i], end = g_off[i + 1];
    float di = g_dinv[i];

    float a[8] = {0.f, 0.f, 0.f, 0.f, 0.f, 0.f, 0.f, 0.f};
    if (w == 0) {   // self loop
        float s = di * di;
        uint2 raw = *((const uint2*)(g_T8 + (size_t)i * DD) + lane);
        float2 f;
        f = up8((u16)(raw.x & 0xffff)); a[0] = s * f.x; a[1] = s * f.y;
        f = up8((u16)(raw.x >> 16));    a[2] = s * f.x; a[3] = s * f.y;
        f = up8((u16)(raw.y & 0xffff)); a[4] = s * f.x; a[5] = s * f.y;
        f = up8((u16)(raw.y >> 16));    a[6] = s * f.x; a[7] = s * f.y;
    }
    int e = beg + w;
    for (; e + 12 < end; e += 16) {
        EdgeRec r0 = g_edges[e];
        EdgeRec r1 = g_edges[e + 4];
        EdgeRec r2 = g_edges[e + 8];
        EdgeRec r3 = g_edges[e + 12];
        uint2 w0 = __ldg((const uint2*)(g_T8 + (size_t)r0.src * DD) + lane);
        uint2 w1 = __ldg((const uint2*)(g_T8 + (size_t)r1.src * DD) + lane);
        uint2 w2 = __ldg((const uint2*)(g_T8 + (size_t)r2.src * DD) + lane);
        uint2 w3 = __ldg((const uint2*)(g_T8 + (size_t)r3.src * DD) + lane);
        float2 f;
        f = up8((u16)(w0.x & 0xffff)); a[0] = fmaf(r0.nrm, f.x, a[0]); a[1] = fmaf(r0.nrm, f.y, a[1]);
        f = up8((u16)(w0.x >> 16));    a[2] = fmaf(r0.nrm, f.x, a[2]); a[3] = fmaf(r0.nrm, f.y, a[3]);
        f = up8((u16)(w0.y & 0xffff)); a[4] = fmaf(r0.nrm, f.x, a[4]); a[5] = fmaf(r0.nrm, f.y, a[5]);
        f = up8((u16)(w0.y >> 16));    a[6] = fmaf(r0.nrm, f.x, a[6]); a[7] = fmaf(r0.nrm, f.y, a[7]);
        f = up8((u16)(w1.x & 0xffff)); a[0] = fmaf(r1.nrm, f.x, a[0]); a[1] = fmaf(r1.nrm, f.y, a[1]);
        f = up8((u16)(w1.x >> 16));    a[2] = fmaf(r1.nrm, f.x, a[2]); a[3] = fmaf(r1.nrm, f.y, a[3]);
        f = up8((u16)(w1.y & 0xffff)); a[4] = fmaf(r1.nrm, f.x, a[4]); a[5] = fmaf(r1.nrm, f.y, a[5]);
        f = up8((u16)(w1.y >> 16));    a[6] = fmaf(r1.nrm, f.x, a[6]); a[7] = fmaf(r1.nrm, f.y, a[7]);
        f = up8((u16)(w2.x & 0xffff)); a[0] = fmaf(r2.nrm, f.x, a[0]); a[1] = fmaf(r2.nrm, f.y, a[1]);
        f = up8((u16)(w2.x >> 16));    a[2] = fmaf(r2.nrm, f.x, a[2]); a[3] = fmaf(r2.nrm, f.y, a[3]);
        f = up8((u16)(w2.y & 0xffff)); a[4] = fmaf(r2.nrm, f.x, a[4]); a[5] = fmaf(r2.nrm, f.y, a[5]);
        f = up8((u16)(w2.y >> 16));    a[6] = fmaf(r2.nrm, f.x, a[6]); a[7] = fmaf(r2.nrm, f.y, a[7]);
        f = up8((u16)(w3.x & 0xffff)); a[0] = fmaf(r3.nrm, f.x, a[0]); a[1] = fmaf(r3.nrm, f.y, a[1]);
        f = up8((u16)(w3.x >> 16));    a[2] = fmaf(r3.nrm, f.x, a[2]); a[3] = fmaf(r3.nrm, f.y, a[3]);
        f = up8((u16)(w3.y & 0xffff)); a[4] = fmaf(r3.nrm, f.x, a[4]); a[5] = fmaf(r3.nrm, f.y, a[5]);
        f = up8((u16)(w3.y >> 16));    a[6] = fmaf(r3.nrm, f.x, a[6]); a[7] = fmaf(r3.nrm, f.y, a[7]);
    }
    for (; e < end; e += 4) {
        EdgeRec r = g_edges[e];
        uint2 w0 = __ldg((const uint2*)(g_T8 + (size_t)r.src * DD) + lane);
        float2 f;
        f = up8((u16)(w0.x & 0xffff)); a[0] = fmaf(r.nrm, f.x, a[0]); a[1] = fmaf(r.nrm, f.y, a[1]);
        f = up8((u16)(w0.x >> 16));    a[2] = fmaf(r.nrm, f.x, a[2]); a[3] = fmaf(r.nrm, f.y, a[3]);
        f = up8((u16)(w0.y & 0xffff)); a[4] = fmaf(r.nrm, f.x, a[4]); a[5] = fmaf(r.nrm, f.y, a[5]);
        f = up8((u16)(w0.y >> 16));    a[6] = fmaf(r.nrm, f.x, a[6]); a[7] = fmaf(r.nrm, f.y, a[7]);
    }
    *(float4*)&red[w][lane * 8]     = make_float4(a[0], a[1], a[2], a[3]);
    *(float4*)&red[w][lane * 8 + 4] = make_float4(a[4], a[5], a[6], a[7]);
    __syncthreads();

#pragma unroll
    for (int f = threadIdx.x; f < DD; f += 128) {
        float v = (red[0][f] + red[1][f]) + (red[2][f] + red[3][f]) + bias[f];
        v = v > 0.f ? v : 0.f;
        g_Af[(size_t)i * DD + f] = __float2half(v);
    }
}

// ======================= z0 = Af[N,256] @ fc_w[256,40] -> fp16 ==============
__global__ void __launch_bounds__(256) k_zgemm(const float* __restrict__ W, int n)
{
    __shared__ float wT[CC * DD];
    for (int i = threadIdx.x; i < CC * DD; i += blockDim.x) {
        int k = i / CC, c = i - k * CC;
        wT[c * DD + k] = W[i];
    }
    __syncthreads();
    int wid = threadIdx.x >> 5, lane = threadIdx.x & 31;
    int gw = blockIdx.x * 8 + wid;
    int nw = gridDim.x * 8;
    for (int row = gw; row < n; row += nw) {
        size_t rb = (size_t)row * DD;
        float hv[8];
        for (int s = 0; s < 8; s++)
            hv[s] = __half2float(__ldg(&g_Af[rb + lane + 32 * s]));
        float acc[CC];
        for (int c = 0; c < CC; c++) {
            const float* wr = wT + c * DD + lane;
            float a = hv[0] * wr[0];
            for (int s = 1; s < 8; s++) a = fmaf(hv[s], wr[32 * s], a);
            acc[c] = a;
        }
        for (int off = 16; off; off >>= 1)
            for (int c = 0; c < CC; c++)
                acc[c] += __shfl_xor_sync(0xffffffffu, acc[c], off);
        if (lane == 0) {
            __half2* zr = (__half2*)(g_Zh[0] + (size_t)row * CC);
            for (int q = 0; q < CC / 2; q++)
                zr[q] = __float22half2_rn(make_float2(acc[2 * q], acc[2 * q + 1]));
        }
    }
}

// ======================= APPNP step: lane-parallel edge fetch + shfl broadcast =========
__global__ void __launch_bounds__(256) k_prop_appnp(int si, int so, int n)
{
    int gw = (blockIdx.x * blockDim.x + threadIdx.x) >> 5;
    int lane = threadIdx.x & 31;
    if (gw >= n) return;
    const __half* zin = g_Zh[si];
    const __half* z0  = g_Zh[0];
    __half* zout = g_Zh[so];
    int i = gw;
    int beg = g_off[i], end = g_off[i + 1];
    float di = g_dinv[i];
    bool act = lane < (CC / 2);

    float2 a = make_float2(0.f, 0.f);
    if (act) {
        float2 f = __half22float2(*(const __half2*)(zin + (size_t)i * CC + 2 * lane));
        float s = di * di;
        a.x = s * f.x;
        a.y = s * f.y;
    }

    int e = beg;
    while (e < end) {
        int m = end - e; if (m > 32) m = 32;
        int esrc = 0; float enrm = 0.f;
        if (lane < m) {
            EdgeRec er = g_edges[e + lane];
            esrc = er.src; enrm = er.nrm;
        }
        int j = 0;
        for (; j + 4 <= m; j += 4) {
            int s0 = __shfl_sync(0xffffffffu, esrc, j);
            int s1 = __shfl_sync(0xffffffffu, esrc, j + 1);
            int s2 = __shfl_sync(0xffffffffu, esrc, j + 2);
            int s3 = __shfl_sync(0xffffffffu, esrc, j + 3);
            float n0 = __shfl_sync(0xffffffffu, enrm, j);
            float n1 = __shfl_sync(0xffffffffu, enrm, j + 1);
            float n2 = __shfl_sync(0xffffffffu, enrm, j + 2);
            float n3 = __shfl_sync(0xffffffffu, enrm, j + 3);
            if (act) {
                float2 f0 = __half22float2(__ldg((const __half2*)(zin + (size_t)s0 * CC + 2 * lane)));
                float2 f1 = __half22float2(__ldg((const __half2*)(zin + (size_t)s1 * CC + 2 * lane)));
                float2 f2 = __half22float2(__ldg((const __half2*)(zin + (size_t)s2 * CC + 2 * lane)));
                float2 f3 = __half22float2(__ldg((const __half2*)(zin + (size_t)s3 * CC + 2 * lane)));
                a.x = fmaf(n0, f0.x, a.x);  a.y = fmaf(n0, f0.y, a.y);
                a.x = fmaf(n1, f1.x, a.x);  a.y = fmaf(n1, f1.y, a.y);
                a.x = fmaf(n2, f2.x, a.x);  a.y = fmaf(n2, f2.y, a.y);
                a.x = fmaf(n3, f3.x, a.x);  a.y = fmaf(n3, f3.y, a.y);
            }
        }
        for (; j < m; j++) {
            int s0 = __shfl_sync(0xffffffffu, esrc, j);
            float n0 = __shfl_sync(0xffffffffu, enrm, j);
            if (act) {
                float2 f0 = __half22float2(__ldg((const __half2*)(zin + (size_t)s0 * CC + 2 * lane)));
                a.x = fmaf(n0, f0.x, a.x);
                a.y = fmaf(n0, f0.y, a.y);
            }
        }
        e += m;
    }

    if (act) {
        float2 f0 = __half22float2(__ldg((const __half2*)(z0 + (size_t)i * CC + 2 * lane)));
        float2 o = make_float2(0.9f * a.x + 0.1f * f0.x, 0.9f * a.y + 0.1f * f0.y);
        *(__half2*)(zout + (size_t)i * CC + 2 * lane) = __float22half2_rn(o);
    }
}

// ======================= out = log_softmax(z + fc_b) =======================
__global__ void __launch_bounds__(256) k_logsoftmax(int si, const float* __restrict__ b,
                                                    float* __restrict__ out, int n)
{
    int gw = (blockIdx.x * blockDim.x + threadIdx.x) >> 5;
    int lane = threadIdx.x & 31;
    if (gw >= n) return;
    const __half* zr = g_Zh[si] + (size_t)gw * CC;
    bool act = lane < (CC / 2);
    float v0 = -1e30f, v1 = -1e30f;
    if (act) {
        float2 f = __half22float2(*(const __half2*)(zr + 2 * lane));
        v0 = f.x + b[2 * lane];
        v1 = f.y + b[2 * lane + 1];
    }
    float m = fmaxf(v0, v1);
    for (int off = 16; off; off >>= 1)
        m = fmaxf(m, __shfl_xor_sync(0xffffffffu, m, off));
    float s = act ? (expf(v0 - m) + expf(v1 - m)) : 0.f;
    for (int off = 16; off; off >>= 1)
        s += __shfl_xor_sync(0xffffffffu, s, off);
    float ls = m + logf(s);
    if (act) {
        float2* o = (float2*)(out + (size_t)gw * CC + 2 * lane);
        *o = make_float2(v0 - ls, v1 - ls);
    }
}

// ======================= launch =======================
extern "C" void kernel_launch(void* const* d_in, const int* in_sizes, int n_in,
                              void* d_out, int out_size)
{
    const float* x   = (const float*)d_in[0];
    const void*  ei  = d_in[1];
    const float* w1  = (const float*)d_in[2];
    const float* b1  = (const float*)d_in[3];
    const float* w2  = (const float*)d_in[4];
    const float* b2  = (const float*)d_in[5];
    const float* w3  = (const float*)d_in[6];
    const float* b3  = (const float*)d_in[7];
    const float* fcw = (const float*)d_in[8];
    const float* fcb = (const float*)d_in[9];
    float* out = (float*)d_out;

    int n = in_sizes[0] / DD;
    int e = in_sizes[1] / 2;
    int nd = n * DD;
    dim3 gMMA(2, (n + 127) / 128);

    cudaFuncSetAttribute(k_mma, cudaFuncAttributeMaxDynamicSharedMemorySize, SMEM_MMA_TOTAL);

    // GEMM1 at launch slot 4 so ncu samples it
    k_detect<<<1, 256>>>((const long long*)ei, e, n);            // 1
    k_split<<<(nd + 255) / 256, 256>>>(x, nd);                   // 2
    k_wsplit<<<256, 256>>>(w1, 0);                               // 3
    k_mma<<<gMMA, 256, SMEM_MMA_TOTAL>>>(1, 0, n);               // 4  <- ncu
    k_wsplit<<<256, 256>>>(w2, 1);
    k_wsplit<<<256, 256>>>(w3, 2);

    // graph preprocessing
    k_zero_deg<<<(n + 255) / 256, 256>>>(n);
    k_hist<<<4096, 256>>>(ei, e);
    k_dinv<<<(n + 255) / 256, 256>>>(n);
    k_scan<<<1, 1024>>>(n);
    k_fill<<<4096, 256>>>(ei, e);

    // GCN layers: single-pass fp8-gather prop, GEMMs on HMMA
    k_prop_gcn<<<n, 128>>>(b1);
    k_mma<<<gMMA, 256, SMEM_MMA_TOTAL>>>(0, 1, n);
    k_prop_gcn<<<n, 128>>>(b2);
    k_mma<<<gMMA, 256, SMEM_MMA_TOTAL>>>(0, 2, n);
    k_prop_gcn<<<n, 128>>>(b3);   // h0 in g_Af

    // APPNP commuted with fc_w: z0 = h0 @ fc_w (fp16), 10 steps on 40 fp16 features
    k_zgemm<<<1024, 256>>>(fcw, n);
    int cur = 0;
    for (int k = 0; k < 10; k++) {
        int nxt = (k % 2 == 0) ? 1 : 2;
        k_prop_appnp<<<(n + 7) / 8, 256>>>(cur, nxt, n);
        cur = nxt;
    }

    k_logsoftmax<<<(n + 7) / 8, 256>>>(cur, fcb, out, n);
}

// round 17
// speedup vs baseline: 1.5234x; 1.5234x over previous
#include <cuda_runtime.h>
#include <cuda_bf16.h>
#include <cuda_fp16.h>

#define NMAX 100000
#define EMAX 3200000
#define DD 256
#define CC 40

typedef unsigned int u32;

struct __align__(8) EdgeRec { int src; float nrm; };

// ---- static device scratch (allocation-free rule) ----
__device__ int   g_is64;
__device__ int   g_deg[NMAX];
__device__ int   g_off[NMAX + 1];
__device__ int   g_cur[NMAX];
__device__ float g_dinv[NMAX];
__device__ EdgeRec g_edges[EMAX];
__device__ __align__(128) __half g_Th[(size_t)NMAX * DD];   // GEMM output, fp16
__device__ __align__(128) __half g_Af[(size_t)NMAX * DD];   // prop output (activations), fp16
__device__ __align__(128) __half g_Xf[(size_t)NMAX * DD];   // input x, fp16
__device__ __align__(128) __half g_Whf[3 * DD * DD];        // W^T, fp16
__device__ __align__(128) __half g_Zh[3][(size_t)NMAX * CC];  // [0]=z0, [1]/[2]=ping-pong

// ======================= preprocessing =======================
__global__ void k_detect(const long long* ei, int e, int n) {
    __shared__ int bad;
    if (threadIdx.x == 0) bad = 0;
    __syncthreads();
    int m = e < 2048 ? e : 2048;
    int isbad = 0;
    for (int i = threadIdx.x; i < m; i += blockDim.x) {
        long long v = ei[i];
        if (v < 0 || v >= (long long)n) isbad = 1;
    }
    if (isbad) atomicOr(&bad, 1);
    __syncthreads();
    if (threadIdx.x == 0) g_is64 = bad ? 0 : 1;
}

__global__ void k_zero_deg(int n) {
    int i = blockIdx.x * blockDim.x + threadIdx.x;
    if (i < n) g_deg[i] = 0;
}

__global__ void k_hist(const void* ei, int e) {
    int f = g_is64;
    const long long* p64 = (const long long*)ei;
    const int* p32 = (const int*)ei;
    int stride = gridDim.x * blockDim.x;
    for (int i = blockIdx.x * blockDim.x + threadIdx.x; i < e; i += stride) {
        int d = f ? (int)p64[e + i] : p32[e + i];
        atomicAdd(&g_deg[d], 1);
    }
}

__global__ void k_dinv(int n) {
    int i = blockIdx.x * blockDim.x + threadIdx.x;
    if (i < n) g_dinv[i] = rsqrtf((float)(g_deg[i] + 1));
}

__global__ void k_scan(int n) {
    __shared__ int s[1024];
    int t = threadIdx.x;
    int chunk = (n + 1023) >> 10;
    int lo = t * chunk; if (lo > n) lo = n;
    int hi = lo + chunk; if (hi > n) hi = n;
    int sum = 0;
    for (int i = lo; i < hi; i++) sum += g_deg[i];
    s[t] = sum;
    __syncthreads();
    for (int off = 1; off < 1024; off <<= 1) {
        int v = 0;
        if (t >= off) v = s[t - off];
        __syncthreads();
        if (t >= off) s[t] += v;
        __syncthreads();
    }
    int run = s[t] - sum;
    for (int i = lo; i < hi; i++) {
        g_off[i] = run; g_cur[i] = run;
        run += g_deg[i];
    }
    if (t == 0) g_off[n] = s[1023];
}

__global__ void k_fill(const void* ei, int e) {
    int f = g_is64;
    const long long* p64 = (const long long*)ei;
    const int* p32 = (const int*)ei;
    int stride = gridDim.x * blockDim.x;
    for (int i = blockIdx.x * blockDim.x + threadIdx.x; i < e; i += stride) {
        int s, d;
        if (f) { s = (int)p64[i]; d = (int)p64[e + i]; }
        else   { s = p32[i];      d = p32[e + i]; }
        int pos = atomicAdd(&g_cur[d], 1);
        EdgeRec r; r.src = s; r.nrm = g_dinv[s] * g_dinv[d];
        g_edges[pos] = r;
    }
}

// ======================= fp16 conversions =======================
__global__ void k_split(const float* __restrict__ X, int total) {
    int i = blockIdx.x * blockDim.x + threadIdx.x;
    if (i < total) g_Xf[i] = __float2half(X[i]);
}

// W [K=256, N=256] row-major -> W^T fp16 [N][K] at layer slot
__global__ void k_wsplit(const float* __restrict__ W, int layer) {
    int i = blockIdx.x * blockDim.x + threadIdx.x;   // 65536
    int k = i >> 8;
    int n = i & 255;
    g_Whf[layer * (DD * DD) + n * DD + k] = __float2half(W[i]);
}

// ======================= fp16 GEMM: mma.sync + ldmatrix + cp.async double buffer =====
// g_Th[M,256] = fp16( A[M,256] @ W^T )  (W stored [N=256][K=256] K-major)
// CTA tile 128x128, 8 warps of 64x32, K staged 32 wide, 2 smem buffers, 2 CTAs/SM.
#define PAD 40
#define MATB (128 * PAD * 2)               // bytes per matrix per stage = 10240
#define STGB (2 * MATB)                    // bytes per stage (A,B) = 20480
#define SMEM_MMA_TOTAL (2 * STGB)          // 40960 bytes

__device__ __forceinline__ u32 s2u(const void* p) {
    u32 a;
    asm("{ .reg .u64 t; cvta.to.shared.u64 t, %1; cvt.u32.u64 %0, t; }" : "=r"(a) : "l"(p));
    return a;
}

__device__ __forceinline__ void cpa16(u32 dst, const __half* src, int sz) {
    asm volatile("cp.async.cg.shared.global [%0], [%1], 16, %2;"
                 :: "r"(dst), "l"(src), "r"(sz));
}
#define CP_COMMIT() asm volatile("cp.async.commit_group;" ::: "memory")
#define CP_WAIT1()  asm volatile("cp.async.wait_group 1;" ::: "memory")
#define CP_WAIT0()  asm volatile("cp.async.wait_group 0;" ::: "memory")

__device__ __forceinline__ void ldsm_x4(u32* r, u32 saddr) {
    asm volatile("ldmatrix.sync.aligned.m8n8.x4.shared.b16 {%0,%1,%2,%3}, [%4];"
                 : "=r"(r[0]), "=r"(r[1]), "=r"(r[2]), "=r"(r[3]) : "r"(saddr));
}

#define MMA_F16(d, a, b) \
    asm volatile( \
        "mma.sync.aligned.m16n8k16.row.col.f32.f16.f16.f32 " \
        "{%0,%1,%2,%3}, {%4,%5,%6,%7}, {%8,%9}, {%0,%1,%2,%3};" \
        : "+f"((d)[0]), "+f"((d)[1]), "+f"((d)[2]), "+f"((d)[3]) \
        : "r"((a)[0]), "r"((a)[1]), "r"((a)[2]), "r"((a)[3]), \
          "r"((b)[0]), "r"((b)[1]))

__global__ void __launch_bounds__(256, 2) k_mma(int srcX, int layer, int M)
{
    extern __shared__ __half sm[];
    u32 sb = s2u(sm);

    const __half* A = srcX ? g_Xf : g_Af;
    const __half* B = g_Whf + layer * (DD * DD);

    int tid = threadIdx.x;
    int wid = tid >> 5;
    int lane = tid & 31;
    int g = lane >> 2;
    int tg = lane & 3;
    int wm = (wid & 1) * 64;       // warp row block (64 rows)
    int wn = (wid >> 1) * 32;      // warp col block (32 cols)
    int mBase = blockIdx.y * 128;
    int nBase = blockIdx.x * 128;

    float acc[16][4];
#pragma unroll
    for (int i = 0; i < 16; i++)
#pragma unroll
        for (int j = 0; j < 4; j++) acc[i][j] = 0.f;

    // ---- cp.async stage loader: stage buffer buf, K-offset kc ----
    auto load_stage = [&](int buf, int kc) {
        u32 so = sb + (u32)(buf * STGB);
#pragma unroll
        for (int it = tid; it < 512; it += 256) {
            int r = it >> 2;
            int c = (it & 3) * 8;
            int row = mBase + r;
            int sz = (row < M) ? 16 : 0;
            int rc = (row < M) ? row : 0;
            size_t go = (size_t)rc * DD + kc + c;
            u32 d = so + (u32)((r * PAD + c) * 2);
            cpa16(d, A + go, sz);
        }
#pragma unroll
        for (int it = tid; it < 512; it += 256) {
            int r = it >> 2;
            int c = (it & 3) * 8;
            size_t go = (size_t)(nBase + r) * DD + kc + c;
            u32 d = so + (u32)((r * PAD + c) * 2);
            cpa16(d + MATB, B + go, 16);
        }
    };

    load_stage(0, 0);  CP_COMMIT();
    load_stage(1, 32); CP_COMMIT();

    // ldmatrix lane addressing (constant per thread)
    int a_row = (lane & 15);
    int a_k   = (lane >> 4) << 3;
    int b_n   = ((lane >> 4) & 1) * 8 + (lane & 7);
    int b_k   = ((lane >> 3) & 1) << 3;

    for (int s = 0; s < 8; s++) {
        if (s == 7) { CP_WAIT0(); } else { CP_WAIT1(); }
        __syncthreads();
        u32 bufo = sb + (u32)((s & 1) * STGB);
#pragma unroll
        for (int k16 = 0; k16 < 32; k16 += 16) {
            u32 af[4][4], bf[8];
#pragma unroll
            for (int mi = 0; mi < 4; mi++) {
                u32 ad = bufo + (u32)(((wm + mi * 16 + a_row) * PAD + k16 + a_k) * 2);
                ldsm_x4(af[mi], ad);
            }
#pragma unroll
            for (int nb = 0; nb < 2; nb++) {
                u32 bd = bufo + (u32)(((wn + nb * 16 + b_n) * PAD + k16 + b_k) * 2);
                ldsm_x4(bf + nb * 4, bd + MATB);
            }
#pragma unroll
            for (int mi = 0; mi < 4; mi++)
#pragma unroll
                for (int ni = 0; ni < 4; ni++)
                    MMA_F16(acc[mi * 4 + ni], af[mi], bf + ni * 2);
        }
        __syncthreads();
        if (s + 2 < 8) {
            load_stage(s & 1, (s + 2) * 32);
            CP_COMMIT();
        }
    }

    // epilogue: write fp16
#pragma unroll
    for (int mi = 0; mi < 4; mi++) {
#pragma unroll
        for (int ni = 0; ni < 4; ni++) {
            int m0 = mBase + wm + mi * 16 + g;
            int col = nBase + wn + ni * 8 + 2 * tg;
            float* d = acc[mi * 4 + ni];
            if (m0 < M)
                *(__half2*)(g_Th + (size_t)m0 * DD + col) =
                    __float22half2_rn(make_float2(d[0], d[1]));
            if (m0 + 8 < M)
                *(__half2*)(g_Th + (size_t)(m0 + 8) * DD + col) =
                    __float22half2_rn(make_float2(d[2], d[3]));
        }
    }
}

// ======================= GCN propagate (single pass, fp16 gather, unroll 4) ============
// out = relu(A_hat @ Th + b) -> fp16. block = node; warp w handles edges beg+w+4k;
// each warp gathers the full 512B fp16 row as 32 x 16B; smem reduce.
__global__ void __launch_bounds__(128) k_prop_gcn(const float* __restrict__ bias)
{
    __shared__ float red[4][DD];
    int i = blockIdx.x;
    int w = threadIdx.x >> 5;
    int lane = threadIdx.x & 31;
    int beg = g_off[i], end = g_off[i + 1];
    float di = g_dinv[i];

    float a[8] = {0.f, 0.f, 0.f, 0.f, 0.f, 0.f, 0.f, 0.f};
    if (w == 0) {   // self loop
        float s = di * di;
        uint4 raw = *((const uint4*)(g_Th + (size_t)i * DD) + lane);
        const __half2* hp = (const __half2*)&raw;
#pragma unroll
        for (int j = 0; j < 4; j++) {
            float2 f = __half22float2(hp[j]);
            a[2 * j]     = s * f.x;
            a[2 * j + 1] = s * f.y;
        }
    }
    int e = beg + w;
    for (; e + 12 < end; e += 16) {
        EdgeRec r0 = g_edges[e];
        EdgeRec r1 = g_edges[e + 4];
        EdgeRec r2 = g_edges[e + 8];
        EdgeRec r3 = g_edges[e + 12];
        uint4 w0 = __ldg((const uint4*)(g_Th + (size_t)r0.src * DD) + lane);
        uint4 w1 = __ldg((const uint4*)(g_Th + (size_t)r1.src * DD) + lane);
        uint4 w2 = __ldg((const uint4*)(g_Th + (size_t)r2.src * DD) + lane);
        uint4 w3 = __ldg((const uint4*)(g_Th + (size_t)r3.src * DD) + lane);
        const __half2* h0 = (const __half2*)&w0;
        const __half2* h1 = (const __half2*)&w1;
        const __half2* h2 = (const __half2*)&w2;
        const __half2* h3 = (const __half2*)&w3;
#pragma unroll
        for (int j = 0; j < 4; j++) {
            float2 f0 = __half22float2(h0[j]);
            float2 f1 = __half22float2(h1[j]);
            float2 f2 = __half22float2(h2[j]);
            float2 f3 = __half22float2(h3[j]);
            a[2 * j]     = fmaf(r0.nrm, f0.x, a[2 * j]);
            a[2 * j + 1] = fmaf(r0.nrm, f0.y, a[2 * j + 1]);
            a[2 * j]     = fmaf(r1.nrm, f1.x, a[2 * j]);
            a[2 * j + 1] = fmaf(r1.nrm, f1.y, a[2 * j + 1]);
            a[2 * j]     = fmaf(r2.nrm, f2.x, a[2 * j]);
            a[2 * j + 1] = fmaf(r2.nrm, f2.y, a[2 * j + 1]);
            a[2 * j]     = fmaf(r3.nrm, f3.x, a[2 * j]);
            a[2 * j + 1] = fmaf(r3.nrm, f3.y, a[2 * j + 1]);
        }
    }
    for (; e < end; e += 4) {
        EdgeRec r = g_edges[e];
        uint4 w0 = __ldg((const uint4*)(g_Th + (size_t)r.src * DD) + lane);
        const __half2* h0 = (const __half2*)&w0;
#pragma unroll
        for (int j = 0; j < 4; j++) {
            float2 f0 = __half22float2(h0[j]);
            a[2 * j]     = fmaf(r.nrm, f0.x, a[2 * j]);
            a[2 * j + 1] = fmaf(r.nrm, f0.y, a[2 * j + 1]);
        }
    }
    *(float4*)&red[w][lane * 8]     = make_float4(a[0], a[1], a[2], a[3]);
    *(float4*)&red[w][lane * 8 + 4] = make_float4(a[4], a[5], a[6], a[7]);
    __syncthreads();

#pragma unroll
    for (int f = threadIdx.x; f < DD; f += 128) {
        float v = (red[0][f] + red[1][f]) + (red[2][f] + red[3][f]) + bias[f];
        v = v > 0.f ? v : 0.f;
        g_Af[(size_t)i * DD + f] = __float2half(v);
    }
}

// ======================= z0 = Af[N,256] @ fc_w[256,40] -> fp16 ==============
__global__ void __launch_bounds__(256) k_zgemm(const float* __restrict__ W, int n)
{
    __shared__ float wT[CC * DD];
    for (int i = threadIdx.x; i < CC * DD; i += blockDim.x) {
        int k = i / CC, c = i - k * CC;
        wT[c * DD + k] = W[i];
    }
    __syncthreads();
    int wid = threadIdx.x >> 5, lane = threadIdx.x & 31;
    int gw = blockIdx.x * 8 + wid;
    int nw = gridDim.x * 8;
    for (int row = gw; row < n; row += nw) {
        size_t rb = (size_t)row * DD;
        float hv[8];
        for (int s = 0; s < 8; s++)
            hv[s] = __half2float(__ldg(&g_Af[rb + lane + 32 * s]));
        float acc[CC];
        for (int c = 0; c < CC; c++) {
            const float* wr = wT + c * DD + lane;
            float a = hv[0] * wr[0];
            for (int s = 1; s < 8; s++) a = fmaf(hv[s], wr[32 * s], a);
            acc[c] = a;
        }
        for (int off = 16; off; off >>= 1)
            for (int c = 0; c < CC; c++)
                acc[c] += __shfl_xor_sync(0xffffffffu, acc[c], off);
        if (lane == 0) {
            __half2* zr = (__half2*)(g_Zh[0] + (size_t)row * CC);
            for (int q = 0; q < CC / 2; q++)
                zr[q] = __float22half2_rn(make_float2(acc[2 * q], acc[2 * q + 1]));
        }
    }
}

// ======================= APPNP step: lane-parallel edge fetch + shfl broadcast =========
__device__ __forceinline__ float2 appnp_gather(const __half* zin, int i, int beg, int end,
                                               float di, int lane, bool act)
{
    float2 a = make_float2(0.f, 0.f);
    if (act) {
        float2 f = __half22float2(*(const __half2*)(zin + (size_t)i * CC + 2 * lane));
        float s = di * di;
        a.x = s * f.x;
        a.y = s * f.y;
    }
    int e = beg;
    while (e < end) {
        int m = end - e; if (m > 32) m = 32;
        int esrc = 0; float enrm = 0.f;
        if (lane < m) {
            EdgeRec er = g_edges[e + lane];
            esrc = er.src; enrm = er.nrm;
        }
        int j = 0;
        for (; j + 4 <= m; j += 4) {
            int s0 = __shfl_sync(0xffffffffu, esrc, j);
            int s1 = __shfl_sync(0xffffffffu, esrc, j + 1);
            int s2 = __shfl_sync(0xffffffffu, esrc, j + 2);
            int s3 = __shfl_sync(0xffffffffu, esrc, j + 3);
            float n0 = __shfl_sync(0xffffffffu, enrm, j);
            float n1 = __shfl_sync(0xffffffffu, enrm, j + 1);
            float n2 = __shfl_sync(0xffffffffu, enrm, j + 2);
            float n3 = __shfl_sync(0xffffffffu, enrm, j + 3);
            if (act) {
                float2 f0 = __half22float2(__ldg((const __half2*)(zin + (size_t)s0 * CC + 2 * lane)));
                float2 f1 = __half22float2(__ldg((const __half2*)(zin + (size_t)s1 * CC + 2 * lane)));
                float2 f2 = __half22float2(__ldg((const __half2*)(zin + (size_t)s2 * CC + 2 * lane)));
                float2 f3 = __half22float2(__ldg((const __half2*)(zin + (size_t)s3 * CC + 2 * lane)));
                a.x = fmaf(n0, f0.x, a.x);  a.y = fmaf(n0, f0.y, a.y);
                a.x = fmaf(n1, f1.x, a.x);  a.y = fmaf(n1, f1.y, a.y);
                a.x = fmaf(n2, f2.x, a.x);  a.y = fmaf(n2, f2.y, a.y);
                a.x = fmaf(n3, f3.x, a.x);  a.y = fmaf(n3, f3.y, a.y);
            }
        }
        for (; j < m; j++) {
            int s0 = __shfl_sync(0xffffffffu, esrc, j);
            float n0 = __shfl_sync(0xffffffffu, enrm, j);
            if (act) {
                float2 f0 = __half22float2(__ldg((const __half2*)(zin + (size_t)s0 * CC + 2 * lane)));
                a.x = fmaf(n0, f0.x, a.x);
                a.y = fmaf(n0, f0.y, a.y);
            }
        }
        e += m;
    }
    return a;
}

__global__ void __launch_bounds__(256) k_prop_appnp(int si, int so, int n)
{
    int gw = (blockIdx.x * blockDim.x + threadIdx.x) >> 5;
    int lane = threadIdx.x & 31;
    if (gw >= n) return;
    const __half* zin = g_Zh[si];
    int i = gw;
    bool act = lane < (CC / 2);
    float2 a = appnp_gather(zin, i, g_off[i], g_off[i + 1], g_dinv[i], lane, act);
    if (act) {
        float2 f0 = __half22float2(__ldg((const __half2*)(g_Zh[0] + (size_t)i * CC + 2 * lane)));
        float2 o = make_float2(0.9f * a.x + 0.1f * f0.x, 0.9f * a.y + 0.1f * f0.y);
        *(__half2*)(g_Zh[so] + (size_t)i * CC + 2 * lane) = __float22half2_rn(o);
    }
}

// ======================= final APPNP step fused with log_softmax =======================
// out = log_softmax(0.9 * A_hat @ zin + 0.1 * z0 + fc_b)
__global__ void __launch_bounds__(256) k_appnp_lsm(int si, const float* __restrict__ b,
                                                   float* __restrict__ out, int n)
{
    int gw = (blockIdx.x * blockDim.x + threadIdx.x) >> 5;
    int lane = threadIdx.x & 31;
    if (gw >= n) return;
    const __half* zin = g_Zh[si];
    int i = gw;
    bool act = lane < (CC / 2);
    float2 a = appnp_gather(zin, i, g_off[i], g_off[i + 1], g_dinv[i], lane, act);
    float v0 = -1e30f, v1 = -1e30f;
    if (act) {
        float2 f0 = __half22float2(__ldg((const __half2*)(g_Zh[0] + (size_t)i * CC + 2 * lane)));
        v0 = 0.9f * a.x + 0.1f * f0.x + b[2 * lane];
        v1 = 0.9f * a.y + 0.1f * f0.y + b[2 * lane + 1];
    }
    float m = fmaxf(v0, v1);
    for (int off = 16; off; off >>= 1)
        m = fmaxf(m, __shfl_xor_sync(0xffffffffu, m, off));
    float s = act ? (expf(v0 - m) + expf(v1 - m)) : 0.f;
    for (int off = 16; off; off >>= 1)
        s += __shfl_xor_sync(0xffffffffu, s, off);
    float ls = m + logf(s);
    if (act) {
        float2* o = (float2*)(out + (size_t)i * CC + 2 * lane);
        *o = make_float2(v0 - ls, v1 - ls);
    }
}

// ======================= launch =======================
extern "C" void kernel_launch(void* const* d_in, const int* in_sizes, int n_in,
                              void* d_out, int out_size)
{
    const float* x   = (const float*)d_in[0];
    const void*  ei  = d_in[1];
    const float* w1  = (const float*)d_in[2];
    const float* b1  = (const float*)d_in[3];
    const float* w2  = (const float*)d_in[4];
    const float* b2  = (const float*)d_in[5];
    const float* w3  = (const float*)d_in[6];
    const float* b3  = (const float*)d_in[7];
    const float* fcw = (const float*)d_in[8];
    const float* fcb = (const float*)d_in[9];
    float* out = (float*)d_out;

    int n = in_sizes[0] / DD;
    int e = in_sizes[1] / 2;
    int nd = n * DD;
    dim3 gMMA(2, (n + 127) / 128);

    cudaFuncSetAttribute(k_mma, cudaFuncAttributeMaxDynamicSharedMemorySize, SMEM_MMA_TOTAL);

    // GEMM1 at launch slot 4 so ncu samples it
    k_detect<<<1, 256>>>((const long long*)ei, e, n);            // 1
    k_split<<<(nd + 255) / 256, 256>>>(x, nd);                   // 2
    k_wsplit<<<256, 256>>>(w1, 0);                               // 3
    k_mma<<<gMMA, 256, SMEM_MMA_TOTAL>>>(1, 0, n);               // 4  <- ncu
    k_wsplit<<<256, 256>>>(w2, 1);
    k_wsplit<<<256, 256>>>(w3, 2);

    // graph preprocessing
    k_zero_deg<<<(n + 255) / 256, 256>>>(n);
    k_hist<<<4096, 256>>>(ei, e);
    k_dinv<<<(n + 255) / 256, 256>>>(n);
    k_scan<<<1, 1024>>>(n);
    k_fill<<<4096, 256>>>(ei, e);

    // GCN layers: single-pass fp16-gather prop, GEMMs on HMMA
    k_prop_gcn<<<n, 128>>>(b1);
    k_mma<<<gMMA, 256, SMEM_MMA_TOTAL>>>(0, 1, n);
    k_prop_gcn<<<n, 128>>>(b2);
    k_mma<<<gMMA, 256, SMEM_MMA_TOTAL>>>(0, 2, n);
    k_prop_gcn<<<n, 128>>>(b3);   // h0 in g_Af

    // APPNP commuted with fc_w: z0 = h0 @ fc_w (fp16), 9 steps + fused final step
    k_zgemm<<<1024, 256>>>(fcw, n);
    int cur = 0;
    for (int k = 0; k < 9; k++) {
        int nxt = (k % 2 == 0) ? 1 : 2;
        k_prop_appnp<<<(n + 7) / 8, 256>>>(cur, nxt, n);
        cur = nxt;
    }
    k_appnp_lsm<<<(n + 7) / 8, 256>>>(cur, fcb, out, n);
}